// round 15
// baseline (speedup 1.0000x reference)
#include <cuda_runtime.h>
#include <cuda_bf16.h>
#include <math.h>
#include <stdint.h>

#define HID 128
#define CLS 10
#define NMAX 100000
#define EMAX 1600000
#define CMAX 50000
#define GMAX 64
#define SCAN_B 256
#define NTILES 1024

typedef unsigned long long ull;

// ---------------- scratch (device globals) -----------------------------------
__device__ __align__(16) uint32_t g_xb  [(size_t)NMAX * 64]; // bf16 x
__device__ __align__(16) uint32_t g_h1b [(size_t)NMAX * 64]; // bf16 h1
__device__ __align__(16) uint32_t g_h2b [(size_t)NMAX * 64]; // bf16 h2
__device__ __align__(16) uint32_t g_aggb[(size_t)NMAX * 64]; // bf16 neighbor-mean
__device__ __align__(32) uint32_t g_zb[(size_t)CMAX * 8];    // bf16 z=xc@Wl_o
__device__ float g_y[(size_t)CMAX * CLS];                    // fp32 y=xc@Wr_o+b
__device__ __align__(16) uint2 g_bfrag[2 * 16 * 16 * 32];    // bf16 B frags
__device__ int g_off[NMAX + 1];
__device__ int g_cur[NMAX];
__device__ int g_esrt[EMAX];           // PRE-SCALED byte offsets (src << 8)

// single zeroed region: [cnt NMAX][tstate NTILES][gsum][gcnt][done 1]
__device__ int g_zero[NMAX + NTILES + GMAX * CLS + GMAX + 1];
#define Zcnt   (g_zero)
#define Ztst   ((unsigned*)(g_zero + NMAX))
#define Zgsum  ((float*)(g_zero + NMAX + NTILES))
#define Zgcnt  (g_zero + NMAX + NTILES + GMAX * CLS)
#define Zdone  (g_zero + NMAX + NTILES + GMAX * CLS + GMAX)
#define ZTOTAL (NMAX + NTILES + GMAX * CLS + GMAX + 1)

// ---------------- helpers ------------------------------------------------------
__device__ __forceinline__ void mma_bf16(float d[4], const uint32_t a[4],
                                         uint32_t b0, uint32_t b1) {
    asm volatile("mma.sync.aligned.m16n8k16.row.col.f32.bf16.bf16.f32 "
                 "{%0,%1,%2,%3}, {%4,%5,%6,%7}, {%8,%9}, {%0,%1,%2,%3};"
                 : "+f"(d[0]), "+f"(d[1]), "+f"(d[2]), "+f"(d[3])
                 : "r"(a[0]), "r"(a[1]), "r"(a[2]), "r"(a[3]), "r"(b0), "r"(b1));
}
__device__ __forceinline__ void ldsm4(uint32_t r[4], uint32_t saddr) {
    asm volatile("ldmatrix.sync.aligned.m8n8.x4.shared.b16 {%0,%1,%2,%3}, [%4];"
                 : "=r"(r[0]), "=r"(r[1]), "=r"(r[2]), "=r"(r[3]) : "r"(saddr));
}
__device__ __forceinline__ float2 unpbf2(uint32_t u) {
    return __bfloat1622float2(*(__nv_bfloat162*)&u);
}
__device__ __forceinline__ void bf16acc(float4& acc, uint2 u) {
    float2 p = unpbf2(u.x);
    float2 q = unpbf2(u.y);
    acc.x += p.x; acc.y += p.y; acc.z += q.x; acc.w += q.y;
}
__device__ __forceinline__ uint2 packbf(float4 v) {
    __nv_bfloat162 lo = __floats2bfloat162_rn(v.x, v.y);
    __nv_bfloat162 hi = __floats2bfloat162_rn(v.z, v.w);
    uint2 o;
    o.x = *(uint32_t*)&lo;
    o.y = *(uint32_t*)&hi;
    return o;
}
__device__ __forceinline__ uint32_t packbf2(float a, float b) {
    __nv_bfloat162 h = __floats2bfloat162_rn(a, b);
    return *(uint32_t*)&h;
}
__device__ __forceinline__ void st_rel(unsigned* p, unsigned v) {
    asm volatile("st.release.gpu.u32 [%0], %1;" :: "l"(p), "r"(v) : "memory");
}
__device__ __forceinline__ unsigned ld_acq(const unsigned* p) {
    unsigned v;
    asm volatile("ld.acquire.gpu.u32 %0, [%1];" : "=r"(v) : "l"(p) : "memory");
    return v;
}

// ---------------- prep: edge histogram + bf16 B frags + bf16 x ------------------
#define NBFRAG (2 * 16 * 16 * 32)
__global__ void prep_count_kernel(const int* __restrict__ dst,
                                  const float* __restrict__ Wl0, const float* __restrict__ Wr0,
                                  const float* __restrict__ Wl1, const float* __restrict__ Wr1,
                                  const float* __restrict__ x, uint2* __restrict__ xb,
                                  int E, int n) {
    int i = blockIdx.x * blockDim.x + threadIdx.x;
    if (i < E) atomicAdd(&Zcnt[dst[i]], 1);
    if (i < NBFRAG) {
        int lane = i & 31, nt = (i >> 5) & 15, ks = (i >> 9) & 15, layer = i >> 13;
        const float* W = layer ? (ks < 8 ? Wl1 : Wr1) : (ks < 8 ? Wl0 : Wr0);
        int k0 = (ks & 7) * 16 + 2 * (lane & 3);
        int nn = nt * 8 + (lane >> 2);
        uint2 o;
        o.x = packbf2(W[(size_t)k0 * HID + nn],       W[(size_t)(k0 + 1) * HID + nn]);
        o.y = packbf2(W[(size_t)(k0 + 8) * HID + nn], W[(size_t)(k0 + 9) * HID + nn]);
        g_bfrag[i] = o;
    }
    int j = i - NBFRAG;
    if (j >= 0 && j < n * 32) {
        float4 v = *(const float4*)(x + (size_t)j * 4);
        xb[j] = packbf(v);
    }
}

// ---------------- single-pass decoupled-lookback exclusive scan -----------------
__global__ void scan_lookback(const int* __restrict__ in, int* __restrict__ off,
                              int* __restrict__ cur, int m) {
    cudaGridDependencySynchronize();
    __shared__ int sh[SCAN_B];
    __shared__ int s_prev;
    int b = blockIdx.x;
    int i = b * SCAN_B + threadIdx.x;
    int v = (i < m) ? in[i] : 0;
    sh[threadIdx.x] = v;
    __syncthreads();
    #pragma unroll
    for (int o = 1; o < SCAN_B; o <<= 1) {
        int t = (threadIdx.x >= o) ? sh[threadIdx.x - o] : 0;
        __syncthreads();
        sh[threadIdx.x] += t;
        __syncthreads();
    }
    int agg = sh[SCAN_B - 1];
    if (threadIdx.x == 0) {
        if (b == 0) {
            st_rel(&Ztst[0], (2u << 30) | (unsigned)agg);
            s_prev = 0;
        } else {
            st_rel(&Ztst[b], (1u << 30) | (unsigned)agg);
            int prev = 0, j = b - 1;
            while (true) {
                unsigned s;
                do { s = ld_acq(&Ztst[j]); } while ((s >> 30) == 0);
                prev += (int)(s & 0x3FFFFFFFu);
                if ((s >> 30) == 2u) break;
                j--;
            }
            st_rel(&Ztst[b], (2u << 30) | (unsigned)(prev + agg));
            s_prev = prev;
        }
    }
    __syncthreads();
    int excl = s_prev + sh[threadIdx.x] - v;
    if (i < m) {
        off[i] = excl;
        cur[i] = excl;
        if (i == m - 1) off[m] = excl + v;
    }
}

// ---------------- fill edge CSR (4 edges/thread, MLP-4, pre-scaled) -------------
__global__ void fill_kernel(const int* __restrict__ src, const int* __restrict__ dst,
                            int E, int quarter) {
    cudaGridDependencySynchronize();
    int i = blockIdx.x * blockDim.x + threadIdx.x;
    if (i >= quarter) return;
    int idx[4], d[4], p[4];
    #pragma unroll
    for (int q = 0; q < 4; q++) idx[q] = i + q * quarter;
    #pragma unroll
    for (int q = 0; q < 4; q++) d[q] = (idx[q] < E) ? dst[idx[q]] : -1;
    #pragma unroll
    for (int q = 0; q < 4; q++) p[q] = (d[q] >= 0) ? atomicAdd(&g_cur[d[q]], 1) : 0;
    #pragma unroll
    for (int q = 0; q < 4; q++)
        if (d[q] >= 0) g_esrt[p[q]] = src[idx[q]] << 8;
}

// ---------------- gather: warp per node, MLP-8, byte-offset addressing ----------
__global__ __launch_bounds__(512) void gather_kernel(const uint2* __restrict__ tab,
                                                     uint2* __restrict__ aggb, int n) {
    int w = (int)(((unsigned)blockIdx.x * blockDim.x + threadIdx.x) >> 5);
    int lane = threadIdx.x & 31;
    cudaGridDependencySynchronize();
    if (w >= n) return;
    const char* base = (const char*)tab + lane * 8;
    int off = g_off[w], end = g_off[w + 1];
    float4 acc = make_float4(0, 0, 0, 0);
    int j = off;
    for (; j + 8 <= end; j += 8) {
        int s[8];
        uint2 u[8];
        #pragma unroll
        for (int q = 0; q < 8; q++) s[q] = __ldg(g_esrt + j + q);
        #pragma unroll
        for (int q = 0; q < 8; q++) u[q] = __ldg((const uint2*)(base + s[q]));
        #pragma unroll
        for (int q = 0; q < 8; q++) bf16acc(acc, u[q]);
    }
    for (; j + 2 <= end; j += 2) {
        int s0 = __ldg(g_esrt + j), s1 = __ldg(g_esrt + j + 1);
        uint2 u0 = __ldg((const uint2*)(base + s0));
        uint2 u1 = __ldg((const uint2*)(base + s1));
        bf16acc(acc, u0);
        bf16acc(acc, u1);
    }
    if (j < end) {
        int s = __ldg(g_esrt + j);
        bf16acc(acc, __ldg((const uint2*)(base + s)));
    }
    float inv = (end > off) ? 1.0f / (float)(end - off) : 0.0f;
    acc.x *= inv; acc.y *= inv; acc.z *= inv; acc.w *= inv;
    aggb[(size_t)w * 32 + lane] = packbf(acc);
}

// ---------------- GEMM layer: bf16 HMMA + ldmatrix ------------------------------
#define PITCH32 132
__global__ __launch_bounds__(256, 4) void gemm_layer(
    const uint2* __restrict__ aggb, const uint2* __restrict__ selfb,
    const uint2* __restrict__ bfrag, const float* __restrict__ bias,
    uint32_t* __restrict__ houtb, int n)
{
    __shared__ uint32_t smA[64 * PITCH32];
    __shared__ float rowss[64];
    int tid = threadIdx.x, lane = tid & 31, wid = tid >> 5;
    int n0 = blockIdx.x * 64;
    if (tid < 64) rowss[tid] = 0.0f;
    int warp_m = wid >> 2, warp_n = wid & 3;
    float2 bb[4];
    #pragma unroll
    for (int u = 0; u < 4; u++)
        bb[u] = *(const float2*)(bias + warp_n * 32 + u * 8 + (lane & 3) * 2);

    cudaGridDependencySynchronize();

    #pragma unroll
    for (int part = 0; part < 2; part++) {
        const uint2* tab = part ? selfb : aggb;
        for (int r = wid; r < 64; r += 8) {
            int node = n0 + r;
            uint2 u = make_uint2(0, 0);
            if (node < n) u = __ldg(tab + (size_t)node * 32 + lane);
            *(uint2*)&smA[r * PITCH32 + part * 64 + lane * 2] = u;
        }
    }
    __syncthreads();

    uint32_t sbase = (uint32_t)__cvta_generic_to_shared(smA);
    int lrow = lane & 15, khalf = (lane >> 4);
    float d[2][4][4] = {};
    #pragma unroll 4
    for (int ks = 0; ks < 16; ks++) {
        uint32_t a[2][4];
        #pragma unroll
        for (int t = 0; t < 2; t++) {
            int row = warp_m * 32 + t * 16 + lrow;
            uint32_t saddr = sbase + (uint32_t)(row * PITCH32 + ks * 8 + khalf * 4) * 4;
            ldsm4(a[t], saddr);
        }
        #pragma unroll
        for (int u = 0; u < 4; u++) {
            uint2 b = __ldg(&bfrag[(size_t)(ks * 16 + warp_n * 4 + u) * 32 + lane]);
            mma_bf16(d[0][u], a[0], b.x, b.y);
            mma_bf16(d[1][u], a[1], b.x, b.y);
        }
    }

    #pragma unroll
    for (int t = 0; t < 2; t++) {
        float ss0 = 0, ss1 = 0;
        #pragma unroll
        for (int u = 0; u < 4; u++) {
            float c0 = fmaxf(d[t][u][0] + bb[u].x, 0.0f);
            float c1 = fmaxf(d[t][u][1] + bb[u].y, 0.0f);
            float c2 = fmaxf(d[t][u][2] + bb[u].x, 0.0f);
            float c3 = fmaxf(d[t][u][3] + bb[u].y, 0.0f);
            ss0 += c0 * c0 + c1 * c1;
            ss1 += c2 * c2 + c3 * c3;
            d[t][u][0] = c0; d[t][u][1] = c1; d[t][u][2] = c2; d[t][u][3] = c3;
        }
        int lr = (warp_m * 2 + t) * 16 + (lane >> 2);
        atomicAdd(&rowss[lr], ss0);
        atomicAdd(&rowss[lr + 8], ss1);
    }
    __syncthreads();

    #pragma unroll
    for (int t = 0; t < 2; t++) {
        int r1 = (warp_m * 2 + t) * 16 + (lane >> 2);
        float rn0 = rsqrtf(rowss[r1]);
        float rn1 = rsqrtf(rowss[r1 + 8]);
        #pragma unroll
        for (int u = 0; u < 4; u++) {
            int cp = warp_n * 16 + u * 4 + (lane & 3);
            smA[r1 * PITCH32 + cp]       = packbf2(d[t][u][0] * rn0, d[t][u][1] * rn0);
            smA[(r1 + 8) * PITCH32 + cp] = packbf2(d[t][u][2] * rn1, d[t][u][3] * rn1);
        }
    }
    __syncthreads();

    #pragma unroll
    for (int e = 0; e < 16; e++) {
        int p = tid + e * 256;
        int r = p >> 6, cp = p & 63;
        int node = n0 + r;
        if (node >= n) continue;
        houtb[(size_t)node * 64 + cp] = smA[r * PITCH32 + cp];
    }
}

// ---------------- xc + projections: cluster w = nodes {2w, 2w+1} ----------------
__global__ __launch_bounds__(256) void xc_kernel(
    const uint2* __restrict__ h2b, const float* __restrict__ Wl,
    const float* __restrict__ Wr, const float* __restrict__ b,
    int n, int Cc)
{
    __shared__ float WlS[HID * CLS];
    __shared__ float WrS[HID * CLS];
    __shared__ float bS[CLS];
    int tid = threadIdx.x;
    for (int i = tid; i < HID * CLS; i += blockDim.x) {
        WlS[i] = Wl[i];
        WrS[i] = Wr[i];
    }
    if (tid < CLS) bS[tid] = b[tid];
    __syncthreads();

    cudaGridDependencySynchronize();

    int w = (int)(((unsigned)blockIdx.x * blockDim.x + tid) >> 5);
    if (w >= Cc) return;
    int lane = tid & 31;
    float4 acc = make_float4(0, 0, 0, 0);
    int cnt = 0;
    if (2 * w < n)     { bf16acc(acc, __ldg(h2b + (size_t)(2 * w)     * 32 + lane)); cnt++; }
    if (2 * w + 1 < n) { bf16acc(acc, __ldg(h2b + (size_t)(2 * w + 1) * 32 + lane)); cnt++; }
    float inv = cnt > 0 ? 1.0f / (float)cnt : 0.0f;
    acc.x *= inv; acc.y *= inv; acc.z *= inv; acc.w *= inv;

    float zv[CLS], yv[CLS];
    int k0 = lane * 4;
    #pragma unroll
    for (int j = 0; j < CLS; j++) {
        zv[j] = acc.x * WlS[(k0 + 0) * CLS + j] + acc.y * WlS[(k0 + 1) * CLS + j]
              + acc.z * WlS[(k0 + 2) * CLS + j] + acc.w * WlS[(k0 + 3) * CLS + j];
        yv[j] = acc.x * WrS[(k0 + 0) * CLS + j] + acc.y * WrS[(k0 + 1) * CLS + j]
              + acc.z * WrS[(k0 + 2) * CLS + j] + acc.w * WrS[(k0 + 3) * CLS + j];
    }
    #pragma unroll
    for (int j = 0; j < CLS; j++) {
        #pragma unroll
        for (int off = 16; off; off >>= 1) {
            zv[j] += __shfl_xor_sync(0xffffffffu, zv[j], off);
            yv[j] += __shfl_xor_sync(0xffffffffu, yv[j], off);
        }
    }
    #pragma unroll
    for (int j = 0; j < 5; j++)
        if (lane == j) g_zb[(size_t)w * 8 + j] = packbf2(zv[2 * j], zv[2 * j + 1]);
    #pragma unroll
    for (int j = 0; j < CLS; j++)
        if (lane == j) g_y[(size_t)w * CLS + j] = yv[j] + bS[j];
}

// ---------------- cluster pool + fused final (last-block) ------------------------
__global__ __launch_bounds__(256) void cluster_pool_kernel(
    const int* __restrict__ bp, float* __restrict__ out, int n, int Cc, int G)
{
    __shared__ int hsh[8][512];
    int tid = threadIdx.x;
    int lane = tid & 31, wid = tid >> 5;
    for (int i = lane; i < 512; i += 32) hsh[wid][i] = 0;
    __syncwarp();

    cudaGridDependencySynchronize();

    int w = (int)(((unsigned)blockIdx.x * blockDim.x + tid) >> 5);
    if (w < Cc) {
        float acc[CLS];
        #pragma unroll
        for (int j = 0; j < CLS; j++) acc[j] = 0.0f;
        int myuniq = 0;

        int nhi = 2 * w + 2;
        if (nhi > n) nhi = n;
        int eb = g_off[2 * w], ee = g_off[nhi];
        for (int j0 = eb; j0 < ee; j0 += 32) {
            int j = j0 + lane;
            if (j < ee) {
                int cu = g_esrt[j] >> 9;
                int key = cu + 1;
                unsigned h = ((unsigned)cu * 2654435761u) >> 23;
                h &= 511;
                int isnew = 0;
                while (true) {
                    int old = atomicCAS(&hsh[wid][h], 0, key);
                    if (old == 0) { isnew = 1; break; }
                    if (old == key) break;
                    h = (h + 1) & 511;
                }
                if (isnew) {
                    myuniq++;
                    const uint32_t* zr = g_zb + (size_t)cu * 8;
                    uint4 a = *(const uint4*)zr;
                    uint32_t a4 = __ldg(zr + 4);
                    float2 p;
                    p = unpbf2(a.x); acc[0] += p.x; acc[1] += p.y;
                    p = unpbf2(a.y); acc[2] += p.x; acc[3] += p.y;
                    p = unpbf2(a.z); acc[4] += p.x; acc[5] += p.y;
                    p = unpbf2(a.w); acc[6] += p.x; acc[7] += p.y;
                    p = unpbf2(a4);  acc[8] += p.x; acc[9] += p.y;
                }
            }
        }
        #pragma unroll
        for (int j = 0; j < CLS; j++) {
            #pragma unroll
            for (int off = 16; off; off >>= 1)
                acc[j] += __shfl_xor_sync(0xffffffffu, acc[j], off);
        }
        #pragma unroll
        for (int off = 16; off; off >>= 1)
            myuniq += __shfl_xor_sync(0xffffffffu, myuniq, off);

        float inv = myuniq > 0 ? 1.0f / (float)myuniq : 0.0f;
        float c[CLS];
        float ss = 0.0f;
        #pragma unroll
        for (int j = 0; j < CLS; j++) {
            c[j] = acc[j] * inv + __ldg(g_y + (size_t)w * CLS + j);
            ss += c[j] * c[j];
        }
        float rn = rsqrtf(ss);
        int g = __ldg(bp + w);
        if (lane < CLS) atomicAdd(&Zgsum[g * CLS + lane], c[lane] * rn);
        if (lane == 0) atomicAdd(&Zgcnt[g], 1);
    }

    // fused final: last block computes log-softmax
    __shared__ int s_last;
    __threadfence();
    __syncthreads();
    if (tid == 0) s_last = (atomicAdd(Zdone, 1) == (int)gridDim.x - 1);
    __syncthreads();
    if (s_last && tid < G) {
        int g = tid;
        int cnt = Zgcnt[g];
        float inv = cnt > 0 ? 1.0f / (float)cnt : 0.0f;
        float v[CLS];
        float mx = -1e30f;
        #pragma unroll
        for (int j = 0; j < CLS; j++) {
            v[j] = Zgsum[g * CLS + j] * inv;
            mx = fmaxf(mx, v[j]);
        }
        float s = 0.0f;
        #pragma unroll
        for (int j = 0; j < CLS; j++) s += expf(v[j] - mx);
        float lse = logf(s) + mx;
        #pragma unroll
        for (int j = 0; j < CLS; j++) out[g * CLS + j] = v[j] - lse;
    }
}

// ---------------- launch ---------------------------------------------------------
template <typename K, typename... Args>
static void pdl_launch(K kernel, dim3 grid, dim3 block, Args... args) {
    cudaLaunchConfig_t cfg = {};
    cfg.gridDim = grid;
    cfg.blockDim = block;
    cudaLaunchAttribute attr[1];
    attr[0].id = cudaLaunchAttributeProgrammaticStreamSerialization;
    attr[0].val.programmaticStreamSerializationAllowed = 1;
    cfg.attrs = attr;
    cfg.numAttrs = 1;
    cudaLaunchKernelEx(&cfg, kernel, args...);
}

extern "C" void kernel_launch(void* const* d_in, const int* in_sizes, int n_in,
                              void* d_out, int out_size) {
    const float* x     = (const float*)d_in[0];
    const float* Wl_in = (const float*)d_in[1];
    const float* Wr_in = (const float*)d_in[2];
    const float* b_in  = (const float*)d_in[3];
    const float* Wl_h  = (const float*)d_in[4];
    const float* Wr_h  = (const float*)d_in[5];
    const float* b_h   = (const float*)d_in[6];
    const float* Wl_o  = (const float*)d_in[7];
    const float* Wr_o  = (const float*)d_in[8];
    const float* b_o   = (const float*)d_in[9];
    const int* esrc = (const int*)d_in[10];
    const int* edst = (const int*)d_in[11];
    const int* bp   = (const int*)d_in[13];

    int n  = in_sizes[0] / HID;
    int E  = in_sizes[10];
    int Cc = in_sizes[13];
    int G  = out_size / CLS;
    float* out = (float*)d_out;

    void *p_zero, *p_off, *p_cur, *p_xb, *p_h1b, *p_h2b, *p_aggb, *p_bfrag;
    cudaGetSymbolAddress(&p_zero,  g_zero);
    cudaGetSymbolAddress(&p_off,   g_off);
    cudaGetSymbolAddress(&p_cur,   g_cur);
    cudaGetSymbolAddress(&p_xb,    g_xb);
    cudaGetSymbolAddress(&p_h1b,   g_h1b);
    cudaGetSymbolAddress(&p_h2b,   g_h2b);
    cudaGetSymbolAddress(&p_aggb,  g_aggb);
    cudaGetSymbolAddress(&p_bfrag, g_bfrag);

    cudaMemsetAsync(p_zero, 0, (size_t)ZTOTAL * sizeof(int));

    int pthreads = NBFRAG + n * 32;
    if (pthreads < E) pthreads = E;
    prep_count_kernel<<<(pthreads + 255) / 256, 256>>>(
        edst, Wl_in, Wr_in, Wl_h, Wr_h, x, (uint2*)p_xb, E, n);

    int nb = (n + SCAN_B - 1) / SCAN_B;
    pdl_launch(scan_lookback, dim3(nb), dim3(SCAN_B),
               (const int*)p_zero, (int*)p_off, (int*)p_cur, n);

    int quarter = (E + 3) / 4;
    pdl_launch(fill_kernel, dim3((quarter + 255) / 256), dim3(256),
               esrc, edst, E, quarter);

    const uint2* bfrag = (const uint2*)p_bfrag;
    int tiles = (n + 63) / 64;
    int gwb = (n + 15) / 16;

    // layer 1
    pdl_launch(gather_kernel, dim3(gwb), dim3(512),
               (const uint2*)p_xb, (uint2*)p_aggb, n);
    pdl_launch(gemm_layer, dim3(tiles), dim3(256),
               (const uint2*)p_aggb, (const uint2*)p_xb, bfrag, b_in,
               (uint32_t*)p_h1b, n);
    // layer 2
    pdl_launch(gather_kernel, dim3(gwb), dim3(512),
               (const uint2*)p_h1b, (uint2*)p_aggb, n);
    pdl_launch(gemm_layer, dim3(tiles), dim3(256),
               (const uint2*)p_aggb, (const uint2*)p_h1b, bfrag + 16 * 16 * 32, b_h,
               (uint32_t*)p_h2b, n);

    // cluster stage (pool has fused final)
    pdl_launch(xc_kernel, dim3((Cc + 7) / 8), dim3(256),
               (const uint2*)p_h2b, Wl_o, Wr_o, b_o, n, Cc);
    pdl_launch(cluster_pool_kernel, dim3((Cc + 7) / 8), dim3(256),
               bp, out, n, Cc, G);
}

// round 16
// speedup vs baseline: 1.0283x; 1.0283x over previous
#include <cuda_runtime.h>
#include <cuda_bf16.h>
#include <math.h>
#include <stdint.h>

#define HID 128
#define CLS 10
#define NMAX 100000
#define EMAX 1600000
#define CMAX 50000
#define GMAX 64
#define SCAN_B 256
#define NTILES 1024

typedef unsigned long long ull;

// ---------------- scratch (device globals) -----------------------------------
__device__ __align__(16) uint32_t g_xb  [(size_t)NMAX * 64]; // bf16 x
__device__ __align__(16) uint32_t g_h1b [(size_t)NMAX * 64]; // bf16 h1
__device__ __align__(16) uint32_t g_h2b [(size_t)NMAX * 64]; // bf16 h2
__device__ __align__(16) uint32_t g_aggb[(size_t)NMAX * 64]; // bf16 neighbor-mean
__device__ __align__(32) uint32_t g_zb[(size_t)CMAX * 8];    // bf16 z=xc@Wl_o
__device__ float g_y[(size_t)CMAX * CLS];                    // fp32 y=xc@Wr_o+b
__device__ __align__(16) uint2 g_bfrag[2 * 16 * 16 * 32];    // bf16 B frags
__device__ int g_off[NMAX + 1];
__device__ int g_cur[NMAX];
__device__ int g_esrt[EMAX];           // PRE-SCALED byte offsets (src << 8)

// single zeroed region: [cnt NMAX][tstate NTILES][gsum][gcnt]
__device__ int g_zero[NMAX + NTILES + GMAX * CLS + GMAX];
#define Zcnt   (g_zero)
#define Ztst   ((unsigned*)(g_zero + NMAX))
#define Zgsum  ((float*)(g_zero + NMAX + NTILES))
#define Zgcnt  (g_zero + NMAX + NTILES + GMAX * CLS)
#define ZTOTAL (NMAX + NTILES + GMAX * CLS + GMAX)

// ---------------- helpers ------------------------------------------------------
__device__ __forceinline__ void mma_bf16(float d[4], const uint32_t a[4],
                                         uint32_t b0, uint32_t b1) {
    asm volatile("mma.sync.aligned.m16n8k16.row.col.f32.bf16.bf16.f32 "
                 "{%0,%1,%2,%3}, {%4,%5,%6,%7}, {%8,%9}, {%0,%1,%2,%3};"
                 : "+f"(d[0]), "+f"(d[1]), "+f"(d[2]), "+f"(d[3])
                 : "r"(a[0]), "r"(a[1]), "r"(a[2]), "r"(a[3]), "r"(b0), "r"(b1));
}
__device__ __forceinline__ void ldsm4(uint32_t r[4], uint32_t saddr) {
    asm volatile("ldmatrix.sync.aligned.m8n8.x4.shared.b16 {%0,%1,%2,%3}, [%4];"
                 : "=r"(r[0]), "=r"(r[1]), "=r"(r[2]), "=r"(r[3]) : "r"(saddr));
}
__device__ __forceinline__ float2 unpbf2(uint32_t u) {
    return __bfloat1622float2(*(__nv_bfloat162*)&u);
}
__device__ __forceinline__ void bf16acc(float4& acc, uint2 u) {
    float2 p = unpbf2(u.x);
    float2 q = unpbf2(u.y);
    acc.x += p.x; acc.y += p.y; acc.z += q.x; acc.w += q.y;
}
__device__ __forceinline__ uint2 packbf(float4 v) {
    __nv_bfloat162 lo = __floats2bfloat162_rn(v.x, v.y);
    __nv_bfloat162 hi = __floats2bfloat162_rn(v.z, v.w);
    uint2 o;
    o.x = *(uint32_t*)&lo;
    o.y = *(uint32_t*)&hi;
    return o;
}
__device__ __forceinline__ uint32_t packbf2(float a, float b) {
    __nv_bfloat162 h = __floats2bfloat162_rn(a, b);
    return *(uint32_t*)&h;
}
__device__ __forceinline__ void st_rel(unsigned* p, unsigned v) {
    asm volatile("st.release.gpu.u32 [%0], %1;" :: "l"(p), "r"(v) : "memory");
}
__device__ __forceinline__ unsigned ld_acq(const unsigned* p) {
    unsigned v;
    asm volatile("ld.acquire.gpu.u32 %0, [%1];" : "=r"(v) : "l"(p) : "memory");
    return v;
}

// ---------------- prep: edge histogram + bf16 B frags + bf16 x ------------------
#define NBFRAG (2 * 16 * 16 * 32)
__global__ void prep_count_kernel(const int* __restrict__ dst,
                                  const float* __restrict__ Wl0, const float* __restrict__ Wr0,
                                  const float* __restrict__ Wl1, const float* __restrict__ Wr1,
                                  const float* __restrict__ x, uint2* __restrict__ xb,
                                  int E, int n) {
    int i = blockIdx.x * blockDim.x + threadIdx.x;
    if (i < E) atomicAdd(&Zcnt[dst[i]], 1);
    if (i < NBFRAG) {
        int lane = i & 31, nt = (i >> 5) & 15, ks = (i >> 9) & 15, layer = i >> 13;
        const float* W = layer ? (ks < 8 ? Wl1 : Wr1) : (ks < 8 ? Wl0 : Wr0);
        int k0 = (ks & 7) * 16 + 2 * (lane & 3);
        int nn = nt * 8 + (lane >> 2);
        uint2 o;
        o.x = packbf2(W[(size_t)k0 * HID + nn],       W[(size_t)(k0 + 1) * HID + nn]);
        o.y = packbf2(W[(size_t)(k0 + 8) * HID + nn], W[(size_t)(k0 + 9) * HID + nn]);
        g_bfrag[i] = o;
    }
    int j = i - NBFRAG;
    if (j >= 0 && j < n * 32) {
        float4 v = *(const float4*)(x + (size_t)j * 4);
        xb[j] = packbf(v);
    }
}

// ---------------- single-pass decoupled-lookback exclusive scan -----------------
__global__ void scan_lookback(const int* __restrict__ in, int* __restrict__ off,
                              int* __restrict__ cur, int m) {
    cudaGridDependencySynchronize();
    __shared__ int sh[SCAN_B];
    __shared__ int s_prev;
    int b = blockIdx.x;
    int i = b * SCAN_B + threadIdx.x;
    int v = (i < m) ? in[i] : 0;
    sh[threadIdx.x] = v;
    __syncthreads();
    #pragma unroll
    for (int o = 1; o < SCAN_B; o <<= 1) {
        int t = (threadIdx.x >= o) ? sh[threadIdx.x - o] : 0;
        __syncthreads();
        sh[threadIdx.x] += t;
        __syncthreads();
    }
    int agg = sh[SCAN_B - 1];
    if (threadIdx.x == 0) {
        if (b == 0) {
            st_rel(&Ztst[0], (2u << 30) | (unsigned)agg);
            s_prev = 0;
        } else {
            st_rel(&Ztst[b], (1u << 30) | (unsigned)agg);
            int prev = 0, j = b - 1;
            while (true) {
                unsigned s;
                do { s = ld_acq(&Ztst[j]); } while ((s >> 30) == 0);
                prev += (int)(s & 0x3FFFFFFFu);
                if ((s >> 30) == 2u) break;
                j--;
            }
            st_rel(&Ztst[b], (2u << 30) | (unsigned)(prev + agg));
            s_prev = prev;
        }
    }
    __syncthreads();
    int excl = s_prev + sh[threadIdx.x] - v;
    if (i < m) {
        off[i] = excl;
        cur[i] = excl;
        if (i == m - 1) off[m] = excl + v;
    }
}

// ---------------- fill edge CSR (2 edges/thread, pre-scaled payload) ------------
__global__ void fill_kernel(const int* __restrict__ src, const int* __restrict__ dst,
                            int E, int half) {
    cudaGridDependencySynchronize();
    int i = blockIdx.x * blockDim.x + threadIdx.x;
    if (i >= half) return;
    int d0 = dst[i];
    int i1 = i + half;
    int d1 = (i1 < E) ? dst[i1] : -1;
    int p0 = atomicAdd(&g_cur[d0], 1);
    int p1 = (d1 >= 0) ? atomicAdd(&g_cur[d1], 1) : 0;
    g_esrt[p0] = src[i] << 8;
    if (d1 >= 0) g_esrt[p1] = src[i1] << 8;
}

// ---------------- gather: warp per node, MLP-8, byte-offset addressing ----------
__global__ __launch_bounds__(512) void gather_kernel(const uint2* __restrict__ tab,
                                                     uint2* __restrict__ aggb, int n) {
    int w = (int)(((unsigned)blockIdx.x * blockDim.x + threadIdx.x) >> 5);
    int lane = threadIdx.x & 31;
    cudaGridDependencySynchronize();
    if (w >= n) return;
    const char* base = (const char*)tab + lane * 8;
    int off = g_off[w], end = g_off[w + 1];
    float4 acc = make_float4(0, 0, 0, 0);
    int j = off;
    for (; j + 8 <= end; j += 8) {
        int s[8];
        uint2 u[8];
        #pragma unroll
        for (int q = 0; q < 8; q++) s[q] = __ldg(g_esrt + j + q);
        #pragma unroll
        for (int q = 0; q < 8; q++) u[q] = __ldg((const uint2*)(base + s[q]));
        #pragma unroll
        for (int q = 0; q < 8; q++) bf16acc(acc, u[q]);
    }
    for (; j + 2 <= end; j += 2) {
        int s0 = __ldg(g_esrt + j), s1 = __ldg(g_esrt + j + 1);
        uint2 u0 = __ldg((const uint2*)(base + s0));
        uint2 u1 = __ldg((const uint2*)(base + s1));
        bf16acc(acc, u0);
        bf16acc(acc, u1);
    }
    if (j < end) {
        int s = __ldg(g_esrt + j);
        bf16acc(acc, __ldg((const uint2*)(base + s)));
    }
    float inv = (end > off) ? 1.0f / (float)(end - off) : 0.0f;
    acc.x *= inv; acc.y *= inv; acc.z *= inv; acc.w *= inv;
    aggb[(size_t)w * 32 + lane] = packbf(acc);
}

// ---------------- GEMM layer: bf16 HMMA + ldmatrix ------------------------------
#define PITCH32 132
__global__ __launch_bounds__(256, 4) void gemm_layer(
    const uint2* __restrict__ aggb, const uint2* __restrict__ selfb,
    const uint2* __restrict__ bfrag, const float* __restrict__ bias,
    uint32_t* __restrict__ houtb, int n)
{
    __shared__ uint32_t smA[64 * PITCH32];
    __shared__ float rowss[64];
    int tid = threadIdx.x, lane = tid & 31, wid = tid >> 5;
    int n0 = blockIdx.x * 64;
    if (tid < 64) rowss[tid] = 0.0f;
    int warp_m = wid >> 2, warp_n = wid & 3;
    float2 bb[4];
    #pragma unroll
    for (int u = 0; u < 4; u++)
        bb[u] = *(const float2*)(bias + warp_n * 32 + u * 8 + (lane & 3) * 2);

    cudaGridDependencySynchronize();

    #pragma unroll
    for (int part = 0; part < 2; part++) {
        const uint2* tab = part ? selfb : aggb;
        for (int r = wid; r < 64; r += 8) {
            int node = n0 + r;
            uint2 u = make_uint2(0, 0);
            if (node < n) u = __ldg(tab + (size_t)node * 32 + lane);
            *(uint2*)&smA[r * PITCH32 + part * 64 + lane * 2] = u;
        }
    }
    __syncthreads();

    uint32_t sbase = (uint32_t)__cvta_generic_to_shared(smA);
    int lrow = lane & 15, khalf = (lane >> 4);
    float d[2][4][4] = {};
    #pragma unroll 4
    for (int ks = 0; ks < 16; ks++) {
        uint32_t a[2][4];
        #pragma unroll
        for (int t = 0; t < 2; t++) {
            int row = warp_m * 32 + t * 16 + lrow;
            uint32_t saddr = sbase + (uint32_t)(row * PITCH32 + ks * 8 + khalf * 4) * 4;
            ldsm4(a[t], saddr);
        }
        #pragma unroll
        for (int u = 0; u < 4; u++) {
            uint2 b = __ldg(&bfrag[(size_t)(ks * 16 + warp_n * 4 + u) * 32 + lane]);
            mma_bf16(d[0][u], a[0], b.x, b.y);
            mma_bf16(d[1][u], a[1], b.x, b.y);
        }
    }

    #pragma unroll
    for (int t = 0; t < 2; t++) {
        float ss0 = 0, ss1 = 0;
        #pragma unroll
        for (int u = 0; u < 4; u++) {
            float c0 = fmaxf(d[t][u][0] + bb[u].x, 0.0f);
            float c1 = fmaxf(d[t][u][1] + bb[u].y, 0.0f);
            float c2 = fmaxf(d[t][u][2] + bb[u].x, 0.0f);
            float c3 = fmaxf(d[t][u][3] + bb[u].y, 0.0f);
            ss0 += c0 * c0 + c1 * c1;
            ss1 += c2 * c2 + c3 * c3;
            d[t][u][0] = c0; d[t][u][1] = c1; d[t][u][2] = c2; d[t][u][3] = c3;
        }
        int lr = (warp_m * 2 + t) * 16 + (lane >> 2);
        atomicAdd(&rowss[lr], ss0);
        atomicAdd(&rowss[lr + 8], ss1);
    }
    __syncthreads();

    #pragma unroll
    for (int t = 0; t < 2; t++) {
        int r1 = (warp_m * 2 + t) * 16 + (lane >> 2);
        float rn0 = rsqrtf(rowss[r1]);
        float rn1 = rsqrtf(rowss[r1 + 8]);
        #pragma unroll
        for (int u = 0; u < 4; u++) {
            int cp = warp_n * 16 + u * 4 + (lane & 3);
            smA[r1 * PITCH32 + cp]       = packbf2(d[t][u][0] * rn0, d[t][u][1] * rn0);
            smA[(r1 + 8) * PITCH32 + cp] = packbf2(d[t][u][2] * rn1, d[t][u][3] * rn1);
        }
    }
    __syncthreads();

    #pragma unroll
    for (int e = 0; e < 16; e++) {
        int p = tid + e * 256;
        int r = p >> 6, cp = p & 63;
        int node = n0 + r;
        if (node >= n) continue;
        houtb[(size_t)node * 64 + cp] = smA[r * PITCH32 + cp];
    }
}

// ---------------- xc + projections: cluster w = nodes {2w, 2w+1} ----------------
__global__ __launch_bounds__(256) void xc_kernel(
    const uint2* __restrict__ h2b, const float* __restrict__ Wl,
    const float* __restrict__ Wr, const float* __restrict__ b,
    int n, int Cc)
{
    __shared__ float WlS[HID * CLS];
    __shared__ float WrS[HID * CLS];
    __shared__ float bS[CLS];
    int tid = threadIdx.x;
    for (int i = tid; i < HID * CLS; i += blockDim.x) {
        WlS[i] = Wl[i];
        WrS[i] = Wr[i];
    }
    if (tid < CLS) bS[tid] = b[tid];
    __syncthreads();

    cudaGridDependencySynchronize();

    int w = (int)(((unsigned)blockIdx.x * blockDim.x + tid) >> 5);
    if (w >= Cc) return;
    int lane = tid & 31;
    float4 acc = make_float4(0, 0, 0, 0);
    int cnt = 0;
    if (2 * w < n)     { bf16acc(acc, __ldg(h2b + (size_t)(2 * w)     * 32 + lane)); cnt++; }
    if (2 * w + 1 < n) { bf16acc(acc, __ldg(h2b + (size_t)(2 * w + 1) * 32 + lane)); cnt++; }
    float inv = cnt > 0 ? 1.0f / (float)cnt : 0.0f;
    acc.x *= inv; acc.y *= inv; acc.z *= inv; acc.w *= inv;

    float zv[CLS], yv[CLS];
    int k0 = lane * 4;
    #pragma unroll
    for (int j = 0; j < CLS; j++) {
        zv[j] = acc.x * WlS[(k0 + 0) * CLS + j] + acc.y * WlS[(k0 + 1) * CLS + j]
              + acc.z * WlS[(k0 + 2) * CLS + j] + acc.w * WlS[(k0 + 3) * CLS + j];
        yv[j] = acc.x * WrS[(k0 + 0) * CLS + j] + acc.y * WrS[(k0 + 1) * CLS + j]
              + acc.z * WrS[(k0 + 2) * CLS + j] + acc.w * WrS[(k0 + 3) * CLS + j];
    }
    #pragma unroll
    for (int j = 0; j < CLS; j++) {
        #pragma unroll
        for (int off = 16; off; off >>= 1) {
            zv[j] += __shfl_xor_sync(0xffffffffu, zv[j], off);
            yv[j] += __shfl_xor_sync(0xffffffffu, yv[j], off);
        }
    }
    #pragma unroll
    for (int j = 0; j < 5; j++)
        if (lane == j) g_zb[(size_t)w * 8 + j] = packbf2(zv[2 * j], zv[2 * j + 1]);
    #pragma unroll
    for (int j = 0; j < CLS; j++)
        if (lane == j) g_y[(size_t)w * CLS + j] = yv[j] + bS[j];
}

// ---------------- cluster pool: contiguous edge range, cu = esrt >> 9 -----------
__global__ __launch_bounds__(256) void cluster_pool_kernel(
    const int* __restrict__ bp, int n, int Cc)
{
    __shared__ int hsh[8][512];
    int tid = threadIdx.x;
    int lane = tid & 31, wid = tid >> 5;
    for (int i = lane; i < 512; i += 32) hsh[wid][i] = 0;
    __syncwarp();

    cudaGridDependencySynchronize();

    int w = (int)(((unsigned)blockIdx.x * blockDim.x + tid) >> 5);
    if (w >= Cc) return;

    float acc[CLS];
    #pragma unroll
    for (int j = 0; j < CLS; j++) acc[j] = 0.0f;
    int myuniq = 0;

    int nhi = 2 * w + 2;
    if (nhi > n) nhi = n;
    int eb = g_off[2 * w], ee = g_off[nhi];
    for (int j0 = eb; j0 < ee; j0 += 32) {
        int j = j0 + lane;
        if (j < ee) {
            int cu = g_esrt[j] >> 9;
            int key = cu + 1;
            unsigned h = ((unsigned)cu * 2654435761u) >> 23;
            h &= 511;
            int isnew = 0;
            while (true) {
                int old = atomicCAS(&hsh[wid][h], 0, key);
                if (old == 0) { isnew = 1; break; }
                if (old == key) break;
                h = (h + 1) & 511;
            }
            if (isnew) {
                myuniq++;
                const uint32_t* zr = g_zb + (size_t)cu * 8;
                uint4 a = *(const uint4*)zr;
                uint32_t a4 = __ldg(zr + 4);
                float2 p;
                p = unpbf2(a.x); acc[0] += p.x; acc[1] += p.y;
                p = unpbf2(a.y); acc[2] += p.x; acc[3] += p.y;
                p = unpbf2(a.z); acc[4] += p.x; acc[5] += p.y;
                p = unpbf2(a.w); acc[6] += p.x; acc[7] += p.y;
                p = unpbf2(a4);  acc[8] += p.x; acc[9] += p.y;
            }
        }
    }
    #pragma unroll
    for (int j = 0; j < CLS; j++) {
        #pragma unroll
        for (int off = 16; off; off >>= 1)
            acc[j] += __shfl_xor_sync(0xffffffffu, acc[j], off);
    }
    #pragma unroll
    for (int off = 16; off; off >>= 1)
        myuniq += __shfl_xor_sync(0xffffffffu, myuniq, off);

    float inv = myuniq > 0 ? 1.0f / (float)myuniq : 0.0f;
    float c[CLS];
    float ss = 0.0f;
    #pragma unroll
    for (int j = 0; j < CLS; j++) {
        c[j] = acc[j] * inv + __ldg(g_y + (size_t)w * CLS + j);
        ss += c[j] * c[j];
    }
    float rn = rsqrtf(ss);
    int g = __ldg(bp + w);
    if (lane < CLS) atomicAdd(&Zgsum[g * CLS + lane], c[lane] * rn);
    if (lane == 0) atomicAdd(&Zgcnt[g], 1);
}

__global__ void final_kernel(float* __restrict__ out, int G) {
    cudaGridDependencySynchronize();
    int g = blockIdx.x * blockDim.x + threadIdx.x;
    if (g >= G) return;
    int cnt = Zgcnt[g];
    float inv = cnt > 0 ? 1.0f / (float)cnt : 0.0f;
    float v[CLS];
    float mx = -1e30f;
    #pragma unroll
    for (int j = 0; j < CLS; j++) { v[j] = Zgsum[g * CLS + j] * inv; mx = fmaxf(mx, v[j]); }
    float s = 0.0f;
    #pragma unroll
    for (int j = 0; j < CLS; j++) s += expf(v[j] - mx);
    float lse = logf(s) + mx;
    #pragma unroll
    for (int j = 0; j < CLS; j++) out[g * CLS + j] = v[j] - lse;
}

// ---------------- launch ---------------------------------------------------------
template <typename K, typename... Args>
static void pdl_launch(K kernel, dim3 grid, dim3 block, Args... args) {
    cudaLaunchConfig_t cfg = {};
    cfg.gridDim = grid;
    cfg.blockDim = block;
    cudaLaunchAttribute attr[1];
    attr[0].id = cudaLaunchAttributeProgrammaticStreamSerialization;
    attr[0].val.programmaticStreamSerializationAllowed = 1;
    cfg.attrs = attr;
    cfg.numAttrs = 1;
    cudaLaunchKernelEx(&cfg, kernel, args...);
}

extern "C" void kernel_launch(void* const* d_in, const int* in_sizes, int n_in,
                              void* d_out, int out_size) {
    const float* x     = (const float*)d_in[0];
    const float* Wl_in = (const float*)d_in[1];
    const float* Wr_in = (const float*)d_in[2];
    const float* b_in  = (const float*)d_in[3];
    const float* Wl_h  = (const float*)d_in[4];
    const float* Wr_h  = (const float*)d_in[5];
    const float* b_h   = (const float*)d_in[6];
    const float* Wl_o  = (const float*)d_in[7];
    const float* Wr_o  = (const float*)d_in[8];
    const float* b_o   = (const float*)d_in[9];
    const int* esrc = (const int*)d_in[10];
    const int* edst = (const int*)d_in[11];
    const int* bp   = (const int*)d_in[13];

    int n  = in_sizes[0] / HID;
    int E  = in_sizes[10];
    int Cc = in_sizes[13];
    int G  = out_size / CLS;
    float* out = (float*)d_out;

    void *p_zero, *p_off, *p_cur, *p_xb, *p_h1b, *p_h2b, *p_aggb, *p_bfrag;
    cudaGetSymbolAddress(&p_zero,  g_zero);
    cudaGetSymbolAddress(&p_off,   g_off);
    cudaGetSymbolAddress(&p_cur,   g_cur);
    cudaGetSymbolAddress(&p_xb,    g_xb);
    cudaGetSymbolAddress(&p_h1b,   g_h1b);
    cudaGetSymbolAddress(&p_h2b,   g_h2b);
    cudaGetSymbolAddress(&p_aggb,  g_aggb);
    cudaGetSymbolAddress(&p_bfrag, g_bfrag);

    cudaMemsetAsync(p_zero, 0, (size_t)ZTOTAL * sizeof(int));

    int pthreads = NBFRAG + n * 32;
    if (pthreads < E) pthreads = E;
    prep_count_kernel<<<(pthreads + 255) / 256, 256>>>(
        edst, Wl_in, Wr_in, Wl_h, Wr_h, x, (uint2*)p_xb, E, n);

    int nb = (n + SCAN_B - 1) / SCAN_B;
    pdl_launch(scan_lookback, dim3(nb), dim3(SCAN_B),
               (const int*)p_zero, (int*)p_off, (int*)p_cur, n);

    int half = (E + 1) / 2;
    pdl_launch(fill_kernel, dim3((half + 255) / 256), dim3(256),
               esrc, edst, E, half);

    const uint2* bfrag = (const uint2*)p_bfrag;
    int tiles = (n + 63) / 64;
    int gwb = (n + 15) / 16;

    // layer 1
    pdl_launch(gather_kernel, dim3(gwb), dim3(512),
               (const uint2*)p_xb, (uint2*)p_aggb, n);
    pdl_launch(gemm_layer, dim3(tiles), dim3(256),
               (const uint2*)p_aggb, (const uint2*)p_xb, bfrag, b_in,
               (uint32_t*)p_h1b, n);
    // layer 2
    pdl_launch(gather_kernel, dim3(gwb), dim3(512),
               (const uint2*)p_h1b, (uint2*)p_aggb, n);
    pdl_launch(gemm_layer, dim3(tiles), dim3(256),
               (const uint2*)p_aggb, (const uint2*)p_h1b, bfrag + 16 * 16 * 32, b_h,
               (uint32_t*)p_h2b, n);

    // cluster stage
    pdl_launch(xc_kernel, dim3((Cc + 7) / 8), dim3(256),
               (const uint2*)p_h2b, Wl_o, Wr_o, b_o, n, Cc);
    pdl_launch(cluster_pool_kernel, dim3((Cc + 7) / 8), dim3(256),
               bp, n, Cc);

    pdl_launch(final_kernel, dim3((G + 63) / 64), dim3(64), out, G);
}